// round 2
// baseline (speedup 1.0000x reference)
#include <cuda_runtime.h>
#include <cstdint>
#include <cstddef>

// Problem dims (fixed by the reference)
#define Bt 1024
#define Tt 512
#define Ii 45
#define Hh 128
#define Oo 45

#define NB  7            // batch rows per CTA
#define NTH 128          // threads per CTA (thread t owns hidden unit j = t)
#define NBLK ((Bt + NB - 1) / NB)   // 147 CTAs

// Shared-memory layout (in floats)
#define OFF_WHH  0                         // W_hh transposed: [k][j], 128*128
#define OFF_WIH  (Hh * Hh)                 // W_ih transposed: [i][j], 45*128
#define OFF_BIAS (OFF_WIH + Ii * Hh)       // b_ih + b_hh, 128
#define OFF_H    (OFF_BIAS + Hh)           // h double buffer: [2][128][8]
#define OFF_X    (OFF_H + 2 * Hh * 8)      // x stage double buffer: [2][48][8]
#define SMEM_FLOATS (OFF_X + 2 * 48 * 8)
#define SMEM_BYTES  (SMEM_FLOATS * 4)      // 100,352 bytes

__global__ void __launch_bounds__(NTH, 1)
rnn_fused_kernel(const float* __restrict__ x,
                 const float* __restrict__ W_ih,
                 const float* __restrict__ b_ih,
                 const float* __restrict__ W_hh,
                 const float* __restrict__ b_hh,
                 const float* __restrict__ W_fc,
                 const float* __restrict__ b_fc,
                 float* __restrict__ out)
{
    extern __shared__ float sm[];
    float* whh_t  = sm + OFF_WHH;
    float* wih_t  = sm + OFF_WIH;
    float* bias_s = sm + OFF_BIAS;
    float* hT     = sm + OFF_H;     // [buf][k][b], b padded to 8
    float* xT     = sm + OFF_X;     // [buf][i][b], i padded to 48, b padded to 8

    const int tid = threadIdx.x;
    const int rowBase = blockIdx.x * NB;

    // ---- Stage weights into SMEM (transposed for conflict-free inner loops) ----
    for (int idx = tid; idx < Hh * Hh; idx += NTH) {
        int jj = idx >> 7;
        int kk = idx & (Hh - 1);
        whh_t[kk * Hh + jj] = W_hh[idx];        // whh_t[k][j] = W_hh[j][k]
    }
    for (int idx = tid; idx < Hh * Ii; idx += NTH) {
        int jj = idx / Ii;
        int ii = idx - jj * Ii;
        wih_t[ii * Hh + jj] = W_ih[idx];        // wih_t[i][j] = W_ih[j][i]
    }
    if (tid < Hh) bias_s[tid] = b_ih[tid] + b_hh[tid];
    // h0 = 0 (buffer 0)
    for (int idx = tid; idx < Hh * 8; idx += NTH) hT[idx] = 0.0f;

    // ---- x stager: each thread owns up to 3 of the NB*Ii = 315 elements ----
    const int e0 = tid, e1 = tid + NTH, e2 = tid + 2 * NTH;
    const bool a0 = e0 < NB * Ii, a1 = e1 < NB * Ii, a2 = e2 < NB * Ii;
    const int b0 = e0 / Ii, b1 = e1 / Ii, b2 = e2 / Ii;
    const int i0 = e0 - b0 * Ii, i1 = e1 - b1 * Ii, i2 = e2 - b2 * Ii;
    const bool val0 = a0 && (rowBase + b0 < Bt);
    const bool val1 = a1 && (rowBase + b1 < Bt);
    const bool val2 = a2 && (rowBase + b2 < Bt);
    const float* g0 = x + ((size_t)(rowBase + b0) * Tt) * Ii + i0;
    const float* g1 = x + ((size_t)(rowBase + b1) * Tt) * Ii + i1;
    const float* g2 = x + ((size_t)(rowBase + b2) * Tt) * Ii + i2;
    const int s0 = i0 * 8 + b0, s1 = i1 * 8 + b1, s2 = i2 * 8 + b2;

    // Stage x for t = 0 into buffer 0
    if (a0) xT[s0] = val0 ? g0[0] : 0.0f;
    if (a1) xT[s1] = val1 ? g1[0] : 0.0f;
    if (a2) xT[s2] = val2 ? g2[0] : 0.0f;
    __syncthreads();

    const int j = tid;                 // hidden unit owned by this thread
    const float bi = bias_s[j];

    for (int t = 0; t < Tt; ++t) {
        const int cur = t & 1;
        const float* hcur = hT + cur * (Hh * 8);
        const float* xcur = xT + cur * (48 * 8);

        // Prefetch next-step x (latency hidden behind the FMA loops below)
        float n0 = 0.0f, n1 = 0.0f, n2 = 0.0f;
        if (t + 1 < Tt) {
            const int off = (t + 1) * Ii;
            if (val0) n0 = g0[off];
            if (val1) n1 = g1[off];
            if (val2) n2 = g2[off];
        }

        float acc0 = bi, acc1 = bi, acc2 = bi, acc3 = bi;
        float acc4 = bi, acc5 = bi, acc6 = bi;

        // Input contribution: acc[b] += W_ih[j][i] * x[b][t][i]
        #pragma unroll
        for (int i = 0; i < Ii; ++i) {
            const float w = wih_t[i * Hh + j];
            const float4 xa = *reinterpret_cast<const float4*>(xcur + i * 8);
            const float4 xb = *reinterpret_cast<const float4*>(xcur + i * 8 + 4);
            acc0 = fmaf(w, xa.x, acc0);
            acc1 = fmaf(w, xa.y, acc1);
            acc2 = fmaf(w, xa.z, acc2);
            acc3 = fmaf(w, xa.w, acc3);
            acc4 = fmaf(w, xb.x, acc4);
            acc5 = fmaf(w, xb.y, acc5);
            acc6 = fmaf(w, xb.z, acc6);
        }

        // Recurrent contribution: acc[b] += W_hh[j][k] * h[b][k]
        #pragma unroll 8
        for (int k = 0; k < Hh; ++k) {
            const float w = whh_t[k * Hh + j];
            const float4 ha = *reinterpret_cast<const float4*>(hcur + k * 8);
            const float4 hb = *reinterpret_cast<const float4*>(hcur + k * 8 + 4);
            acc0 = fmaf(w, ha.x, acc0);
            acc1 = fmaf(w, ha.y, acc1);
            acc2 = fmaf(w, ha.z, acc2);
            acc3 = fmaf(w, ha.w, acc3);
            acc4 = fmaf(w, hb.x, acc4);
            acc5 = fmaf(w, hb.y, acc5);
            acc6 = fmaf(w, hb.z, acc6);
        }

        // h_new = tanh(acc); write to the other buffer (transposed [k][b])
        float4 o1, o2;
        o1.x = tanhf(acc0); o1.y = tanhf(acc1);
        o1.z = tanhf(acc2); o1.w = tanhf(acc3);
        o2.x = tanhf(acc4); o2.y = tanhf(acc5);
        o2.z = tanhf(acc6); o2.w = 0.0f;
        float* hn = hT + (cur ^ 1) * (Hh * 8) + j * 8;
        *reinterpret_cast<float4*>(hn)     = o1;
        *reinterpret_cast<float4*>(hn + 4) = o2;

        // Store prefetched x into the other buffer
        float* xn = xT + (cur ^ 1) * (48 * 8);
        if (a0) xn[s0] = n0;
        if (a1) xn[s1] = n1;
        if (a2) xn[s2] = n2;

        __syncthreads();   // one barrier per step: next buffers fully written
    }

    // ---- Final FC: out[b][o] = b_fc[o] + sum_j W_fc[o][j] * h_last[b][j] ----
    // Tt is even, so the last write (t = 511) landed in buffer 0.
    const float* hlast = hT;
    for (int idx = tid; idx < NB * Oo; idx += NTH) {
        const int b = idx / Oo;
        const int o = idx - b * Oo;
        const int row = rowBase + b;
        if (row < Bt) {
            float s = b_fc[o];
            const float* wp = W_fc + o * Hh;
            #pragma unroll 8
            for (int jj = 0; jj < Hh; ++jj)
                s = fmaf(wp[jj], hlast[jj * 8 + b], s);
            out[row * Oo + o] = s;
        }
    }
}

extern "C" void kernel_launch(void* const* d_in, const int* in_sizes, int n_in,
                              void* d_out, int out_size)
{
    const float* x   = (const float*)d_in[0];
    const float* Wih = (const float*)d_in[1];
    const float* bih = (const float*)d_in[2];
    const float* Whh = (const float*)d_in[3];
    const float* bhh = (const float*)d_in[4];
    const float* Wfc = (const float*)d_in[5];
    const float* bfc = (const float*)d_in[6];
    float* out = (float*)d_out;

    cudaFuncSetAttribute(rnn_fused_kernel,
                         cudaFuncAttributeMaxDynamicSharedMemorySize, SMEM_BYTES);
    rnn_fused_kernel<<<NBLK, NTH, SMEM_BYTES>>>(x, Wih, bih, Whh, bhh, Wfc, bfc, out);
}